// round 1
// baseline (speedup 1.0000x reference)
#include <cuda_runtime.h>
#include <math.h>

// Model dims
#define QL 512
#define BS 8
#define VC 32000
#define DM 1024
#define NH 16
#define DHD 64
#define FFD 4096
#define NL 4
#define RL 513         // klen+1 relative positions
#define TOK 4096       // QL*BS
#define BH 128         // BS*NH
#define ATT_SCALE 0.125f  // 1/sqrt(64)

// ---------------------------------------------------------------------------
// Scratch (device globals; no allocation allowed in kernel_launch)
// ---------------------------------------------------------------------------
__device__ float g_core[TOK * DM];          // residual stream        16 MB
__device__ float g_big[TOK * FFD];          // qkv (4096x3072) / ffn hidden (4096x4096)  64 MB
__device__ float g_vec[TOK * DM];           // attn vec / src2        16 MB
__device__ float g_tmp[TOK * DM];           // attn_out / ffn out     16 MB
__device__ float g_h[TOK * DM];             // post-norm1 hidden      16 MB
__device__ float g_r[RL * DM];              // positional embeddings   2 MB
__device__ float g_rqkv[RL * 3 * DM];       // r @ Wqkv                6 MB
__device__ float g_qr[(size_t)BH * QL * RL];    // BD pre-shift      135 MB
__device__ float g_score[(size_t)BH * QL * QL]; // attn scores/probs 134 MB

// ---------------------------------------------------------------------------
// Embedding lookup * sqrt(D)
// ---------------------------------------------------------------------------
__global__ void k_embed(const int* __restrict__ src, const float* __restrict__ emb) {
    int t = blockIdx.x;                 // t = i*BS + b
    int tok = src[t];
    const float4* e = (const float4*)(emb + (size_t)tok * DM);
    float4* o = (float4*)(g_core + (size_t)t * DM);
    for (int d = threadIdx.x; d < DM / 4; d += blockDim.x) {
        float4 v = e[d];
        v.x *= 32.f; v.y *= 32.f; v.z *= 32.f; v.w *= 32.f;
        o[d] = v;
    }
}

// ---------------------------------------------------------------------------
// Sinusoidal positional embedding. pos_seq = klen..0, r = [sin | cos]
// ---------------------------------------------------------------------------
__global__ void k_posemb() {
    int p = blockIdx.x;                 // 0..512
    double pos = (double)(QL - p);      // klen - p
    for (int d = threadIdx.x; d < DM; d += blockDim.x) {
        int j = d & 511;
        double inv = exp(-((double)(2 * j) / (double)DM) * log(10000.0));
        double a = pos * inv;
        g_r[p * DM + d] = (d < 512) ? (float)sin(a) : (float)cos(a);
    }
}

// ---------------------------------------------------------------------------
// Generic SGEMM:  C[M,N] = act(A[M,K] @ op(B) + bias)
//   TB=false: B is (K,N) row-major.  TB=true: B is (N,K) row-major (NT).
//   ACT: 0 = none, 1 = exact GELU
//   Tiles: 128x128x16, 256 threads, 8x8 per thread.
//   Requires: K % 16 == 0, N % 128 == 0. M arbitrary (row-guarded).
// ---------------------------------------------------------------------------
template <int ACT, bool TB>
__global__ __launch_bounds__(256, 2)
void k_sgemm(const float* __restrict__ A, const float* __restrict__ B,
             const float* __restrict__ bias, float* __restrict__ C,
             int M, int N, int K) {
    __shared__ float As[16][128];
    __shared__ float Bs[16][128];
    int tid = threadIdx.x;
    int m0 = blockIdx.y << 7, n0 = blockIdx.x << 7;
    int ty = tid >> 4, tx = tid & 15;

    float acc[8][8];
#pragma unroll
    for (int i = 0; i < 8; i++)
#pragma unroll
        for (int j = 0; j < 8; j++) acc[i][j] = 0.f;

    for (int k0 = 0; k0 < K; k0 += 16) {
#pragma unroll
        for (int u = 0; u < 2; u++) {
            int idx4 = tid * 2 + u;
            // A tile: 128 rows x 16 cols, stored transposed As[k][m]
            int ml = idx4 >> 2, kq = idx4 & 3;
            float4 va = make_float4(0.f, 0.f, 0.f, 0.f);
            if (m0 + ml < M)
                va = *(const float4*)(A + (size_t)(m0 + ml) * K + k0 + kq * 4);
            As[kq * 4 + 0][ml] = va.x;
            As[kq * 4 + 1][ml] = va.y;
            As[kq * 4 + 2][ml] = va.z;
            As[kq * 4 + 3][ml] = va.w;
            if (!TB) {
                int kr = idx4 >> 5, nq = idx4 & 31;
                float4 vb = *(const float4*)(B + (size_t)(k0 + kr) * N + n0 + nq * 4);
                *(float4*)&Bs[kr][nq * 4] = vb;
            } else {
                int nl = idx4 >> 2, kq2 = idx4 & 3;
                float4 vb = *(const float4*)(B + (size_t)(n0 + nl) * K + k0 + kq2 * 4);
                Bs[kq2 * 4 + 0][nl] = vb.x;
                Bs[kq2 * 4 + 1][nl] = vb.y;
                Bs[kq2 * 4 + 2][nl] = vb.z;
                Bs[kq2 * 4 + 3][nl] = vb.w;
            }
        }
        __syncthreads();
#pragma unroll
        for (int k = 0; k < 16; k++) {
            float4 a0 = *(const float4*)&As[k][ty * 8];
            float4 a1 = *(const float4*)&As[k][ty * 8 + 4];
            float4 b0 = *(const float4*)&Bs[k][tx * 8];
            float4 b1 = *(const float4*)&Bs[k][tx * 8 + 4];
            float ar[8] = {a0.x, a0.y, a0.z, a0.w, a1.x, a1.y, a1.z, a1.w};
            float br[8] = {b0.x, b0.y, b0.z, b0.w, b1.x, b1.y, b1.z, b1.w};
#pragma unroll
            for (int i = 0; i < 8; i++)
#pragma unroll
                for (int j = 0; j < 8; j++)
                    acc[i][j] += ar[i] * br[j];
        }
        __syncthreads();
    }

#pragma unroll
    for (int i = 0; i < 8; i++) {
        int m = m0 + ty * 8 + i;
        if (m >= M) continue;
        float* crow = C + (size_t)m * N + n0 + tx * 8;
#pragma unroll
        for (int j4 = 0; j4 < 2; j4++) {
            float v[4];
#pragma unroll
            for (int c = 0; c < 4; c++) {
                float x = acc[i][j4 * 4 + c];
                if (bias) x += bias[n0 + tx * 8 + j4 * 4 + c];
                if (ACT == 1) x = 0.5f * x * (1.f + erff(x * 0.70710678118654752f));
                v[c] = x;
            }
            *(float4*)(crow + j4 * 4) = make_float4(v[0], v[1], v[2], v[3]);
        }
    }
}

// ---------------------------------------------------------------------------
// 64x64 tile MMA contracting over the padded 64-wide second index (NT form)
// ---------------------------------------------------------------------------
__device__ __forceinline__ void mma_nt64(const float (*X)[68], const float (*Y)[68],
                                         int ty, int tx, float acc[4][4]) {
#pragma unroll
    for (int d4 = 0; d4 < 16; d4++) {
        float4 xv[4], yv[4];
#pragma unroll
        for (int ii = 0; ii < 4; ii++) xv[ii] = *(const float4*)&X[ty * 4 + ii][d4 * 4];
#pragma unroll
        for (int jj = 0; jj < 4; jj++) yv[jj] = *(const float4*)&Y[tx * 4 + jj][d4 * 4];
#pragma unroll
        for (int ii = 0; ii < 4; ii++)
#pragma unroll
            for (int jj = 0; jj < 4; jj++)
                acc[ii][jj] += xv[ii].x * yv[jj].x + xv[ii].y * yv[jj].y +
                               xv[ii].z * yv[jj].z + xv[ii].w * yv[jj].w;
    }
}

// ---------------------------------------------------------------------------
// qr[bn, i, jr] = sum_d (wq[i,b,n,d] + rq_last[n,d]) * rk[jr,n,d]
// Only jr >= 512 - i is ever consumed -> skip far tiles.
// grid (9, 8, 128), 256 threads
// ---------------------------------------------------------------------------
__global__ __launch_bounds__(256) void k_qr() {
    int bn = blockIdx.z, b = bn >> 4, n = bn & 15;
    int i0 = blockIdx.y << 6, jr0 = blockIdx.x << 6;
    if (jr0 + i0 + 126 < QL) return;  // entire tile unused by rel-shift gather
    __shared__ float Qs[64][68], Rs[64][68];
    int tid = threadIdx.x;
    const float* rql = g_rqkv + (size_t)QL * 3 * DM + n * DHD;  // rq row klen
#pragma unroll
    for (int u = 0; u < 16; u++) {
        int idx = tid + u * 256;
        int rr = idx >> 6, d = idx & 63;
        Qs[rr][d] = g_big[((size_t)(i0 + rr) * BS + b) * (3 * DM) + n * DHD + d] + rql[d];
        int jr = jr0 + rr;
        Rs[rr][d] = (jr < RL) ? g_rqkv[(size_t)jr * (3 * DM) + DM + n * DHD + d] : 0.f;
    }
    __syncthreads();
    int ty = tid >> 4, tx = tid & 15;
    float acc[4][4] = {};
    mma_nt64(Qs, Rs, ty, tx, acc);
    float* out = g_qr + (size_t)bn * QL * RL;
#pragma unroll
    for (int ii = 0; ii < 4; ii++) {
        int i = i0 + ty * 4 + ii;
#pragma unroll
        for (int jj = 0; jj < 4; jj++) {
            int jr = jr0 + tx * 4 + jj;
            if (jr < RL) out[(size_t)i * RL + jr] = acc[ii][jj];
        }
    }
}

// ---------------------------------------------------------------------------
// score[bn, i, j] = (AC + BD) * SCALE, masked (-inf for j > i)
// AC = q_bias . wk ; BD = qr[i, klen + j - i]
// grid (8, 8, 128)
// ---------------------------------------------------------------------------
__global__ __launch_bounds__(256) void k_score() {
    int bn = blockIdx.z, b = bn >> 4, n = bn & 15;
    int i0 = blockIdx.y << 6, j0 = blockIdx.x << 6;
    int tid = threadIdx.x, ty = tid >> 4, tx = tid & 15;
    float* srow = g_score + (size_t)bn * QL * QL;
    if (j0 > i0 + 63) {  // fully masked tile: write -inf, skip compute
#pragma unroll
        for (int ii = 0; ii < 4; ii++) {
            int i = i0 + ty * 4 + ii;
            *(float4*)&srow[(size_t)i * QL + j0 + tx * 4] =
                make_float4(-INFINITY, -INFINITY, -INFINITY, -INFINITY);
        }
        return;
    }
    __shared__ float Qs[64][68], Ks[64][68];
    const float* rql = g_rqkv + (size_t)QL * 3 * DM + n * DHD;
#pragma unroll
    for (int u = 0; u < 16; u++) {
        int idx = tid + u * 256;
        int rr = idx >> 6, d = idx & 63;
        Qs[rr][d] = g_big[((size_t)(i0 + rr) * BS + b) * (3 * DM) + n * DHD + d] + rql[d];
        Ks[rr][d] = g_big[((size_t)(j0 + rr) * BS + b) * (3 * DM) + DM + n * DHD + d];
    }
    __syncthreads();
    float acc[4][4] = {};
    mma_nt64(Qs, Ks, ty, tx, acc);
    const float* qrb = g_qr + (size_t)bn * QL * RL;
#pragma unroll
    for (int ii = 0; ii < 4; ii++) {
        int i = i0 + ty * 4 + ii;
        float v[4];
#pragma unroll
        for (int jj = 0; jj < 4; jj++) {
            int j = j0 + tx * 4 + jj;
            if (j > i) v[jj] = -INFINITY;
            else v[jj] = (acc[ii][jj] + qrb[(size_t)i * RL + (QL + j - i)]) * ATT_SCALE;
        }
        *(float4*)&srow[(size_t)i * QL + j0 + tx * 4] = make_float4(v[0], v[1], v[2], v[3]);
    }
}

// ---------------------------------------------------------------------------
// Row softmax over key dim (512). One block per (bn, i) row.
// ---------------------------------------------------------------------------
__global__ __launch_bounds__(256) void k_softmax() {
    float* p = g_score + (size_t)blockIdx.x * QL;
    int tid = threadIdx.x;
    float v0 = p[tid], v1 = p[tid + 256];
    __shared__ float red[256];
    red[tid] = fmaxf(v0, v1);
    __syncthreads();
    for (int st = 128; st > 0; st >>= 1) {
        if (tid < st) red[tid] = fmaxf(red[tid], red[tid + st]);
        __syncthreads();
    }
    float mx = red[0];
    __syncthreads();
    float e0 = expf(v0 - mx), e1 = expf(v1 - mx);
    red[tid] = e0 + e1;
    __syncthreads();
    for (int st = 128; st > 0; st >>= 1) {
        if (tid < st) red[tid] += red[tid + st];
        __syncthreads();
    }
    float inv = 1.f / red[0];
    p[tid] = e0 * inv;
    p[tid + 256] = e1 * inv;
}

// ---------------------------------------------------------------------------
// vec[i,b, n*64+d] = sum_j prob[bn,i,j] * wv[j,b,n,d]
// Causal: prob is 0 for j > i, so the k-loop stops at the diagonal tile.
// grid (8, 128)
// ---------------------------------------------------------------------------
__global__ __launch_bounds__(256) void k_av() {
    int bn = blockIdx.y, b = bn >> 4, n = bn & 15;
    int i0 = blockIdx.x << 6;
    __shared__ float Ps[64][68], Vs[64][68];
    int tid = threadIdx.x, ty = tid >> 4, tx = tid & 15;
    float acc[4][4] = {};
    const float* prow = g_score + (size_t)bn * QL * QL;
    int kend = i0 + 64;
    for (int k0 = 0; k0 < kend; k0 += 64) {
#pragma unroll
        for (int u = 0; u < 16; u++) {
            int idx = tid + u * 256;
            int rr = idx >> 6, c = idx & 63;
            Ps[rr][c] = prow[(size_t)(i0 + rr) * QL + k0 + c];
            Vs[rr][c] = g_big[((size_t)(k0 + rr) * BS + b) * (3 * DM) + 2 * DM + n * DHD + c];
        }
        __syncthreads();
#pragma unroll
        for (int k4 = 0; k4 < 16; k4++) {
            float4 pr[4];
#pragma unroll
            for (int ii = 0; ii < 4; ii++) pr[ii] = *(const float4*)&Ps[ty * 4 + ii][k4 * 4];
#pragma unroll
            for (int kk = 0; kk < 4; kk++) {
                float4 vv = *(const float4*)&Vs[k4 * 4 + kk][tx * 4];
#pragma unroll
                for (int ii = 0; ii < 4; ii++) {
                    float pv = ((const float*)&pr[ii])[kk];
                    acc[ii][0] += pv * vv.x;
                    acc[ii][1] += pv * vv.y;
                    acc[ii][2] += pv * vv.z;
                    acc[ii][3] += pv * vv.w;
                }
            }
        }
        __syncthreads();
    }
#pragma unroll
    for (int ii = 0; ii < 4; ii++) {
        int i = i0 + ty * 4 + ii;
        float* o = g_vec + ((size_t)i * BS + b) * DM + n * DHD + tx * 4;
        *(float4*)o = make_float4(acc[ii][0], acc[ii][1], acc[ii][2], acc[ii][3]);
    }
}

// ---------------------------------------------------------------------------
// O = LayerNorm(A + B) * gamma + beta   (row = one token, D = 1024)
// ---------------------------------------------------------------------------
__global__ __launch_bounds__(256) void k_lnres(const float* __restrict__ A,
                                               const float* __restrict__ Bi,
                                               const float* __restrict__ G,
                                               const float* __restrict__ Be,
                                               float* __restrict__ O) {
    int row = blockIdx.x, tid = threadIdx.x;
    const float* a = A + (size_t)row * DM;
    const float* bb = Bi + (size_t)row * DM;
    float x[4];
    float s = 0.f, s2 = 0.f;
#pragma unroll
    for (int u = 0; u < 4; u++) {
        int c = tid + u * 256;
        float v = a[c] + bb[c];
        x[u] = v;
        s += v;
        s2 += v * v;
    }
    __shared__ float rs[256], rs2[256];
    rs[tid] = s;
    rs2[tid] = s2;
    __syncthreads();
    for (int st = 128; st > 0; st >>= 1) {
        if (tid < st) { rs[tid] += rs[tid + st]; rs2[tid] += rs2[tid + st]; }
        __syncthreads();
    }
    float mean = rs[0] * (1.f / (float)DM);
    float var = rs2[0] * (1.f / (float)DM) - mean * mean;
    float inv = rsqrtf(var + 1e-5f);
    float* o = O + (size_t)row * DM;
#pragma unroll
    for (int u = 0; u < 4; u++) {
        int c = tid + u * 256;
        o[c] = (x[u] - mean) * inv * G[c] + Be[c];
    }
}

// ---------------------------------------------------------------------------
// Launch sequence
// ---------------------------------------------------------------------------
extern "C" void kernel_launch(void* const* d_in, const int* in_sizes, int n_in,
                              void* d_out, int out_size) {
    const int*   src   = (const int*)d_in[0];
    const float* emb   = (const float*)d_in[1];
    const float* dec_b = (const float*)d_in[2];
    const float* Wqkv  = (const float*)d_in[3];
    const float* Wo    = (const float*)d_in[4];
    const float* ln0_g = (const float*)d_in[5];
    const float* ln0_b = (const float*)d_in[6];
    const float* W1    = (const float*)d_in[7];
    const float* b1    = (const float*)d_in[8];
    const float* W2    = (const float*)d_in[9];
    const float* b2    = (const float*)d_in[10];
    const float* ln1_g = (const float*)d_in[11];
    const float* ln1_b = (const float*)d_in[12];
    const float* ln2_g = (const float*)d_in[13];
    const float* ln2_b = (const float*)d_in[14];
    float* out = (float*)d_out;

    float *core, *big, *vec, *tmp, *h, *r, *rqkv;
    cudaGetSymbolAddress((void**)&core, g_core);
    cudaGetSymbolAddress((void**)&big,  g_big);
    cudaGetSymbolAddress((void**)&vec,  g_vec);
    cudaGetSymbolAddress((void**)&tmp,  g_tmp);
    cudaGetSymbolAddress((void**)&h,    g_h);
    cudaGetSymbolAddress((void**)&r,    g_r);
    cudaGetSymbolAddress((void**)&rqkv, g_rqkv);

    k_embed<<<TOK, 256>>>(src, emb);
    k_posemb<<<RL, 256>>>();

    for (int l = 0; l < NL; l++) {
        const float* Wq = Wqkv + (size_t)l * DM * 3 * DM;
        // qkv = core @ Wqkv[l]                        (4096 x 3072 x 1024)
        k_sgemm<0, false><<<dim3(3 * DM / 128, TOK / 128), 256>>>(
            core, Wq, nullptr, big, TOK, 3 * DM, DM);
        // rqkv = r @ Wqkv[l]                          (513 x 3072 x 1024)
        k_sgemm<0, false><<<dim3(3 * DM / 128, (RL + 127) / 128), 256>>>(
            r, Wq, nullptr, rqkv, RL, 3 * DM, DM);
        // attention
        k_qr<<<dim3(9, 8, BH), 256>>>();
        k_score<<<dim3(8, 8, BH), 256>>>();
        k_softmax<<<BH * QL, 256>>>();
        k_av<<<dim3(8, BH), 256>>>();
        // attn_out = vec @ Wo[l]
        k_sgemm<0, false><<<dim3(DM / 128, TOK / 128), 256>>>(
            vec, Wo + (size_t)l * DM * DM, nullptr, tmp, TOK, DM, DM);
        // src2 = LN(core + attn_out); h = LN(core + src2)
        k_lnres<<<TOK, 256>>>(core, tmp, ln0_g + l * DM, ln0_b + l * DM, vec);
        k_lnres<<<TOK, 256>>>(core, vec, ln1_g + l * DM, ln1_b + l * DM, h);
        // ffn = gelu(h @ W1 + b1) @ W2 + b2
        k_sgemm<1, false><<<dim3(FFD / 128, TOK / 128), 256>>>(
            h, W1 + (size_t)l * DM * FFD, b1 + (size_t)l * FFD, big, TOK, FFD, DM);
        k_sgemm<0, false><<<dim3(DM / 128, TOK / 128), 256>>>(
            big, W2 + (size_t)l * FFD * DM, b2 + (size_t)l * DM, tmp, TOK, DM, FFD);
        // core = LN(h + ffn)
        k_lnres<<<TOK, 256>>>(h, tmp, ln2_g + l * DM, ln2_b + l * DM, core);
    }

    // logits = core @ emb^T + dec_b                   (4096 x 32000 x 1024, NT)
    k_sgemm<0, true><<<dim3(VC / 128, TOK / 128), 256>>>(
        core, emb, dec_b, out, TOK, VC, DM);
}

// round 5
// speedup vs baseline: 2.1717x; 2.1717x over previous
#include <cuda_runtime.h>
#include <cuda_bf16.h>
#include <math.h>
#include <stdint.h>

// Model dims
#define QL 512
#define BS 8
#define VC 32000
#define DM 1024
#define NH 16
#define DHD 64
#define FFD 4096
#define NL 4
#define RL 513
#define TOK 4096
#define BH 128
#define ATT_SCALE 0.125f

// ---------------------------------------------------------------------------
// Scratch
// ---------------------------------------------------------------------------
__device__ float g_core[TOK * DM];
__device__ float g_big[TOK * FFD];
__device__ float g_vec[TOK * DM];
__device__ float g_tmp[TOK * DM];
__device__ float g_h[TOK * DM];
__device__ float g_r[RL * DM];
__device__ float g_rqkv[RL * 3 * DM];
__device__ float g_qr[(size_t)BH * QL * RL];
__device__ float g_score[(size_t)BH * QL * QL];
// bf16 split buffers
__device__ __nv_bfloat16 g_ah[TOK * FFD];        // activations hi (max 4096x4096)
__device__ __nv_bfloat16 g_al[TOK * FFD];
__device__ __nv_bfloat16 g_wh[DM * FFD];         // weights hi (max 1024x4096)
__device__ __nv_bfloat16 g_wl[DM * FFD];
__device__ __nv_bfloat16 g_eh[(size_t)VC * DM];  // embedding hi
__device__ __nv_bfloat16 g_el[(size_t)VC * DM];
__device__ __nv_bfloat16 g_rh[RL * DM];
__device__ __nv_bfloat16 g_rl[RL * DM];

static __device__ __forceinline__ uint32_t s2u(const void* p) {
    return (uint32_t)__cvta_generic_to_shared(p);
}

#define LDSM4(R, addr)                                                           \
    asm volatile("ldmatrix.sync.aligned.m8n8.x4.shared.b16 {%0,%1,%2,%3}, [%4];" \
                 : "=r"(R[0]), "=r"(R[1]), "=r"(R[2]), "=r"(R[3]) : "r"(addr));
#define LDSM4T(R, addr)                                                                \
    asm volatile("ldmatrix.sync.aligned.m8n8.x4.trans.shared.b16 {%0,%1,%2,%3}, [%4];" \
                 : "=r"(R[0]), "=r"(R[1]), "=r"(R[2]), "=r"(R[3]) : "r"(addr));
#define MMA_BF16(ac, A, b0, b1)                                                  \
    asm volatile("mma.sync.aligned.m16n8k16.row.col.f32.bf16.bf16.f32 "          \
                 "{%0,%1,%2,%3}, {%4,%5,%6,%7}, {%8,%9}, {%0,%1,%2,%3};"         \
                 : "+f"(ac[0]), "+f"(ac[1]), "+f"(ac[2]), "+f"(ac[3])            \
                 : "r"(A[0]), "r"(A[1]), "r"(A[2]), "r"(A[3]), "r"(b0), "r"(b1));

// ---------------------------------------------------------------------------
// Split fp32 -> (hi, lo) bf16.  x ~= hi + lo with ~16-bit effective mantissa.
// ---------------------------------------------------------------------------
__global__ void k_split(const float* __restrict__ x, __nv_bfloat16* __restrict__ h,
                        __nv_bfloat16* __restrict__ l, int n) {
    int i = (blockIdx.x * 256 + threadIdx.x) * 4;
    if (i >= n) return;
    float4 v = *(const float4*)(x + i);
    __nv_bfloat16 h0 = __float2bfloat16(v.x);
    __nv_bfloat16 h1 = __float2bfloat16(v.y);
    __nv_bfloat16 h2 = __float2bfloat16(v.z);
    __nv_bfloat16 h3 = __float2bfloat16(v.w);
    __nv_bfloat16 l0 = __float2bfloat16(v.x - __bfloat162float(h0));
    __nv_bfloat16 l1 = __float2bfloat16(v.y - __bfloat162float(h1));
    __nv_bfloat16 l2 = __float2bfloat16(v.z - __bfloat162float(h2));
    __nv_bfloat16 l3 = __float2bfloat16(v.w - __bfloat162float(h3));
    *(__nv_bfloat162*)(h + i)     = __nv_bfloat162(h0, h1);
    *(__nv_bfloat162*)(h + i + 2) = __nv_bfloat162(h2, h3);
    *(__nv_bfloat162*)(l + i)     = __nv_bfloat162(l0, l1);
    *(__nv_bfloat162*)(l + i + 2) = __nv_bfloat162(l2, l3);
}

// ---------------------------------------------------------------------------
// Split-bf16 tensor-core GEMM: C[M,N] = act(A @ op(B) + bias)
//   A given as (Ah, Al) bf16 row-major [M,K]; B as (Bh, Bl):
//     TB=false: [K,N] row-major.  TB=true: [N,K] row-major (NT).
//   C fp32. 128x128x32 tile, 8 warps, mma.m16n8k16, 3 MMAs per fragment pair.
//   Requires K%32==0, N%128==0. M arbitrary.
// ---------------------------------------------------------------------------
template <int ACT, bool TB>
__global__ __launch_bounds__(256, 2)
void k_mgemm(const __nv_bfloat16* __restrict__ Ah, const __nv_bfloat16* __restrict__ Al,
             const __nv_bfloat16* __restrict__ Bh, const __nv_bfloat16* __restrict__ Bl,
             const float* __restrict__ bias, float* __restrict__ C,
             int M, int N, int K) {
    constexpr int BSTR = TB ? 40 : 136;          // smem row stride (halves)
    constexpr int BSIZE = TB ? 128 * 40 : 32 * 136;
    __shared__ __align__(16) __nv_bfloat16 smem[2 * 128 * 40 + 2 * BSIZE];
    __nv_bfloat16* sAh = smem;
    __nv_bfloat16* sAl = smem + 128 * 40;
    __nv_bfloat16* sBh = smem + 2 * 128 * 40;
    __nv_bfloat16* sBl = sBh + BSIZE;

    int tid = threadIdx.x;
    int m0 = blockIdx.y << 7, n0 = blockIdx.x << 7;
    int lane = tid & 31, warp = tid >> 5;
    int wm = warp >> 1, wn = warp & 1;

    float acc[2][8][4];
#pragma unroll
    for (int a = 0; a < 2; a++)
#pragma unroll
        for (int b = 0; b < 8; b++)
#pragma unroll
            for (int c = 0; c < 4; c++) acc[a][b][c] = 0.f;

    for (int k0 = 0; k0 < K; k0 += 32) {
        // ---- A tile 128x32 (hi+lo) ----
#pragma unroll
        for (int u = 0; u < 2; u++) {
            int p = tid + u * 256;
            int row = p >> 2, kq = (p & 3) << 3;
            uint4 vh = make_uint4(0, 0, 0, 0), vl = make_uint4(0, 0, 0, 0);
            if (m0 + row < M) {
                size_t off = (size_t)(m0 + row) * K + k0 + kq;
                vh = *(const uint4*)(Ah + off);
                vl = *(const uint4*)(Al + off);
            }
            *(uint4*)&sAh[row * 40 + kq] = vh;
            *(uint4*)&sAl[row * 40 + kq] = vl;
        }
        // ---- B tile ----
#pragma unroll
        for (int u = 0; u < 2; u++) {
            int p = tid + u * 256;
            if (TB) {
                int row = p >> 2, kq = (p & 3) << 3;
                size_t off = (size_t)(n0 + row) * K + k0 + kq;
                *(uint4*)&sBh[row * 40 + kq] = *(const uint4*)(Bh + off);
                *(uint4*)&sBl[row * 40 + kq] = *(const uint4*)(Bl + off);
            } else {
                int row = p >> 4, nq = (p & 15) << 3;
                size_t off = (size_t)(k0 + row) * N + n0 + nq;
                *(uint4*)&sBh[row * 136 + nq] = *(const uint4*)(Bh + off);
                *(uint4*)&sBl[row * 136 + nq] = *(const uint4*)(Bl + off);
            }
        }
        __syncthreads();

#pragma unroll
        for (int ks = 0; ks < 32; ks += 16) {
            uint32_t ah[2][4], al[2][4];
#pragma unroll
            for (int mt = 0; mt < 2; mt++) {
                int rb = wm * 32 + mt * 16 + (lane & 15);
                int kc = ks + ((lane >> 4) << 3);
                uint32_t adh = s2u(&sAh[rb * 40 + kc]);
                uint32_t adl = s2u(&sAl[rb * 40 + kc]);
                LDSM4(ah[mt], adh);
                LDSM4(al[mt], adl);
            }
#pragma unroll
            for (int np = 0; np < 4; np++) {
                int nb = wn * 64 + np * 16;
                uint32_t bh[4], bl[4];
                int g = lane >> 3, l8 = lane & 7;
                if (TB) {
                    int nr = nb + ((g >> 1) << 3) + l8;
                    int kc = ks + ((g & 1) << 3);
                    uint32_t adh = s2u(&sBh[nr * BSTR + kc]);
                    uint32_t adl = s2u(&sBl[nr * BSTR + kc]);
                    LDSM4(bh, adh);
                    LDSM4(bl, adl);
                } else {
                    int kr = ks + ((g & 1) << 3) + l8;
                    int nc = nb + ((g >> 1) << 3);
                    uint32_t adh = s2u(&sBh[kr * BSTR + nc]);
                    uint32_t adl = s2u(&sBl[kr * BSTR + nc]);
                    LDSM4T(bh, adh);
                    LDSM4T(bl, adl);
                }
#pragma unroll
                for (int mt = 0; mt < 2; mt++) {
#pragma unroll
                    for (int j = 0; j < 2; j++) {
                        float* ac = acc[mt][np * 2 + j];
                        MMA_BF16(ac, ah[mt], bh[2 * j], bh[2 * j + 1]);
                        MMA_BF16(ac, ah[mt], bl[2 * j], bl[2 * j + 1]);
                        MMA_BF16(ac, al[mt], bh[2 * j], bh[2 * j + 1]);
                    }
                }
            }
        }
        __syncthreads();
    }

    // ---- epilogue ----
#pragma unroll
    for (int mt = 0; mt < 2; mt++) {
#pragma unroll
        for (int np = 0; np < 4; np++) {
#pragma unroll
            for (int j = 0; j < 2; j++) {
                int nt = np * 2 + j;
                int col = n0 + wn * 64 + np * 16 + j * 8 + (lane & 3) * 2;
                int rb = m0 + wm * 32 + mt * 16 + (lane >> 2);
#pragma unroll
                for (int hh = 0; hh < 2; hh++) {
                    int r = rb + hh * 8;
                    if (r >= M) continue;
                    float v0 = acc[mt][nt][hh * 2];
                    float v1 = acc[mt][nt][hh * 2 + 1];
                    if (bias) { v0 += bias[col]; v1 += bias[col + 1]; }
                    if (ACT == 1) {
                        v0 = 0.5f * v0 * (1.f + erff(v0 * 0.70710678118654752f));
                        v1 = 0.5f * v1 * (1.f + erff(v1 * 0.70710678118654752f));
                    }
                    *(float2*)(C + (size_t)r * N + col) = make_float2(v0, v1);
                }
            }
        }
    }
}

// ---------------------------------------------------------------------------
// Embedding lookup * sqrt(D)
// ---------------------------------------------------------------------------
__global__ void k_embed(const int* __restrict__ src, const float* __restrict__ emb) {
    int t = blockIdx.x;
    int tok = src[t];
    const float4* e = (const float4*)(emb + (size_t)tok * DM);
    float4* o = (float4*)(g_core + (size_t)t * DM);
    for (int d = threadIdx.x; d < DM / 4; d += blockDim.x) {
        float4 v = e[d];
        v.x *= 32.f; v.y *= 32.f; v.z *= 32.f; v.w *= 32.f;
        o[d] = v;
    }
}

__global__ void k_posemb() {
    int p = blockIdx.x;
    double pos = (double)(QL - p);
    for (int d = threadIdx.x; d < DM; d += blockDim.x) {
        int j = d & 511;
        double inv = exp(-((double)(2 * j) / (double)DM) * log(10000.0));
        double a = pos * inv;
        g_r[p * DM + d] = (d < 512) ? (float)sin(a) : (float)cos(a);
    }
}

// ---------------------------------------------------------------------------
// Attention kernels (fp32)
// ---------------------------------------------------------------------------
__device__ __forceinline__ void mma_nt64(const float (*X)[68], const float (*Y)[68],
                                         int ty, int tx, float acc[4][4]) {
#pragma unroll
    for (int d4 = 0; d4 < 16; d4++) {
        float4 xv[4], yv[4];
#pragma unroll
        for (int ii = 0; ii < 4; ii++) xv[ii] = *(const float4*)&X[ty * 4 + ii][d4 * 4];
#pragma unroll
        for (int jj = 0; jj < 4; jj++) yv[jj] = *(const float4*)&Y[tx * 4 + jj][d4 * 4];
#pragma unroll
        for (int ii = 0; ii < 4; ii++)
#pragma unroll
            for (int jj = 0; jj < 4; jj++)
                acc[ii][jj] += xv[ii].x * yv[jj].x + xv[ii].y * yv[jj].y +
                               xv[ii].z * yv[jj].z + xv[ii].w * yv[jj].w;
    }
}

__global__ __launch_bounds__(256) void k_qr() {
    int bn = blockIdx.z, b = bn >> 4, n = bn & 15;
    int i0 = blockIdx.y << 6, jr0 = blockIdx.x << 6;
    if (jr0 + i0 + 126 < QL) return;
    __shared__ float Qs[64][68], Rs[64][68];
    int tid = threadIdx.x;
    const float* rql = g_rqkv + (size_t)QL * 3 * DM + n * DHD;
#pragma unroll
    for (int u = 0; u < 16; u++) {
        int idx = tid + u * 256;
        int rr = idx >> 6, d = idx & 63;
        Qs[rr][d] = g_big[((size_t)(i0 + rr) * BS + b) * (3 * DM) + n * DHD + d] + rql[d];
        int jr = jr0 + rr;
        Rs[rr][d] = (jr < RL) ? g_rqkv[(size_t)jr * (3 * DM) + DM + n * DHD + d] : 0.f;
    }
    __syncthreads();
    int ty = tid >> 4, tx = tid & 15;
    float acc[4][4] = {};
    mma_nt64(Qs, Rs, ty, tx, acc);
    float* out = g_qr + (size_t)bn * QL * RL;
#pragma unroll
    for (int ii = 0; ii < 4; ii++) {
        int i = i0 + ty * 4 + ii;
#pragma unroll
        for (int jj = 0; jj < 4; jj++) {
            int jr = jr0 + tx * 4 + jj;
            if (jr < RL) out[(size_t)i * RL + jr] = acc[ii][jj];
        }
    }
}

__global__ __launch_bounds__(256) void k_score() {
    int bn = blockIdx.z, b = bn >> 4, n = bn & 15;
    int i0 = blockIdx.y << 6, j0 = blockIdx.x << 6;
    int tid = threadIdx.x, ty = tid >> 4, tx = tid & 15;
    float* srow = g_score + (size_t)bn * QL * QL;
    if (j0 > i0 + 63) {
#pragma unroll
        for (int ii = 0; ii < 4; ii++) {
            int i = i0 + ty * 4 + ii;
            *(float4*)&srow[(size_t)i * QL + j0 + tx * 4] =
                make_float4(-INFINITY, -INFINITY, -INFINITY, -INFINITY);
        }
        return;
    }
    __shared__ float Qs[64][68], Ks[64][68];
    const float* rql = g_rqkv + (size_t)QL * 3 * DM + n * DHD;
#pragma unroll
    for (int u = 0; u < 16; u++) {
        int idx = tid + u * 256;
        int rr = idx >> 6, d = idx & 63;
        Qs[rr][d] = g_big[((size_t)(i0 + rr) * BS + b) * (3 * DM) + n * DHD + d] + rql[d];
        Ks[rr][d] = g_big[((size_t)(j0 + rr) * BS + b) * (3 * DM) + DM + n * DHD + d];
    }
    __syncthreads();
    float acc[4][4] = {};
    mma_nt64(Qs, Ks, ty, tx, acc);
    const float* qrb = g_qr + (size_t)bn * QL * RL;
#pragma unroll
    for (int ii = 0; ii < 4; ii++) {
        int i = i0 + ty * 4 + ii;
        float v[4];
#pragma unroll
        for (int jj = 0; jj < 4; jj++) {
            int j = j0 + tx * 4 + jj;
            if (j > i) v[jj] = -INFINITY;
            else v[jj] = (acc[ii][jj] + qrb[(size_t)i * RL + (QL + j - i)]) * ATT_SCALE;
        }
        *(float4*)&srow[(size_t)i * QL + j0 + tx * 4] = make_float4(v[0], v[1], v[2], v[3]);
    }
}

__global__ __launch_bounds__(256) void k_softmax() {
    float* p = g_score + (size_t)blockIdx.x * QL;
    int tid = threadIdx.x;
    float v0 = p[tid], v1 = p[tid + 256];
    __shared__ float red[256];
    red[tid] = fmaxf(v0, v1);
    __syncthreads();
    for (int st = 128; st > 0; st >>= 1) {
        if (tid < st) red[tid] = fmaxf(red[tid], red[tid + st]);
        __syncthreads();
    }
    float mx = red[0];
    __syncthreads();
    float e0 = expf(v0 - mx), e1 = expf(v1 - mx);
    red[tid] = e0 + e1;
    __syncthreads();
    for (int st = 128; st > 0; st >>= 1) {
        if (tid < st) red[tid] += red[tid + st];
        __syncthreads();
    }
    float inv = 1.f / red[0];
    p[tid] = e0 * inv;
    p[tid + 256] = e1 * inv;
}

__global__ __launch_bounds__(256) void k_av() {
    int bn = blockIdx.y, b = bn >> 4, n = bn & 15;
    int i0 = blockIdx.x << 6;
    __shared__ float Ps[64][68], Vs[64][68];
    int tid = threadIdx.x, ty = tid >> 4, tx = tid & 15;
    float acc[4][4] = {};
    const float* prow = g_score + (size_t)bn * QL * QL;
    int kend = i0 + 64;
    for (int k0 = 0; k0 < kend; k0 += 64) {
#pragma unroll
        for (int u = 0; u < 16; u++) {
            int idx = tid + u * 256;
            int rr = idx >> 6, c = idx & 63;
            Ps[rr][c] = prow[(size_t)(i0 + rr) * QL + k0 + c];
            Vs[rr][c] = g_big[((size_t)(k0 + rr) * BS + b) * (3 * DM) + 2 * DM + n * DHD + c];
        }
        __syncthreads();
#pragma unroll
        for (int k4 = 0; k4 < 16; k4++) {
            float4 pr[4];
#pragma unroll
            for (int ii = 0; ii < 4; ii++) pr[ii] = *(const float4*)&Ps[ty * 4 + ii][k4 * 4];
#pragma unroll
            for (int kk = 0; kk < 4; kk++) {
                float4 vv = *(const float4*)&Vs[k4 * 4 + kk][tx * 4];
#pragma unroll
                for (int ii = 0; ii < 4; ii++) {
                    float pv = ((const float*)&pr[ii])[kk];
                    acc[ii][0] += pv * vv.x;
                    acc[ii][1] += pv * vv.y;
                    acc[ii][2] += pv * vv.z;
                    acc[ii][3] += pv * vv.w;
                }
            }
        }
        __syncthreads();
    }
#pragma unroll
    for (int ii = 0; ii < 4; ii++) {
        int i = i0 + ty * 4 + ii;
        float* o = g_vec + ((size_t)i * BS + b) * DM + n * DHD + tx * 4;
        *(float4*)o = make_float4(acc[ii][0], acc[ii][1], acc[ii][2], acc[ii][3]);
    }
}

// ---------------------------------------------------------------------------
// O = LayerNorm(A + B) * gamma + beta
// ---------------------------------------------------------------------------
__global__ __launch_bounds__(256) void k_lnres(const float* __restrict__ A,
                                               const float* __restrict__ Bi,
                                               const float* __restrict__ G,
                                               const float* __restrict__ Be,
                                               float* __restrict__ O) {
    int row = blockIdx.x, tid = threadIdx.x;
    const float* a = A + (size_t)row * DM;
    const float* bb = Bi + (size_t)row * DM;
    float x[4];
    float s = 0.f, s2 = 0.f;
#pragma unroll
    for (int u = 0; u < 4; u++) {
        int c = tid + u * 256;
        float v = a[c] + bb[c];
        x[u] = v;
        s += v;
        s2 += v * v;
    }
    __shared__ float rs[256], rs2[256];
    rs[tid] = s;
    rs2[tid] = s2;
    __syncthreads();
    for (int st = 128; st > 0; st >>= 1) {
        if (tid < st) { rs[tid] += rs[tid + st]; rs2[tid] += rs2[tid + st]; }
        __syncthreads();
    }
    float mean = rs[0] * (1.f / (float)DM);
    float var = rs2[0] * (1.f / (float)DM) - mean * mean;
    float inv = rsqrtf(var + 1e-5f);
    float* o = O + (size_t)row * DM;
#pragma unroll
    for (int u = 0; u < 4; u++) {
        int c = tid + u * 256;
        o[c] = (x[u] - mean) * inv * G[c] + Be[c];
    }
}

// ---------------------------------------------------------------------------
// Launch sequence
// ---------------------------------------------------------------------------
extern "C" void kernel_launch(void* const* d_in, const int* in_sizes, int n_in,
                              void* d_out, int out_size) {
    const int*   src   = (const int*)d_in[0];
    const float* emb   = (const float*)d_in[1];
    const float* dec_b = (const float*)d_in[2];
    const float* Wqkv  = (const float*)d_in[3];
    const float* Wo    = (const float*)d_in[4];
    const float* ln0_g = (const float*)d_in[5];
    const float* ln0_b = (const float*)d_in[6];
    const float* W1    = (const float*)d_in[7];
    const float* b1    = (const float*)d_in[8];
    const float* W2    = (const float*)d_in[9];
    const float* b2    = (const float*)d_in[10];
    const float* ln1_g = (const float*)d_in[11];
    const float* ln1_b = (const float*)d_in[12];
    const float* ln2_g = (const float*)d_in[13];
    const float* ln2_b = (const float*)d_in[14];
    float* out = (float*)d_out;

    float *core, *big, *vec, *tmp, *h, *r, *rqkv;
    cudaGetSymbolAddress((void**)&core, g_core);
    cudaGetSymbolAddress((void**)&big,  g_big);
    cudaGetSymbolAddress((void**)&vec,  g_vec);
    cudaGetSymbolAddress((void**)&tmp,  g_tmp);
    cudaGetSymbolAddress((void**)&h,    g_h);
    cudaGetSymbolAddress((void**)&r,    g_r);
    cudaGetSymbolAddress((void**)&rqkv, g_rqkv);
    __nv_bfloat16 *ah, *al, *wh, *wl, *eh, *el, *rh, *rl;
    cudaGetSymbolAddress((void**)&ah, g_ah);
    cudaGetSymbolAddress((void**)&al, g_al);
    cudaGetSymbolAddress((void**)&wh, g_wh);
    cudaGetSymbolAddress((void**)&wl, g_wl);
    cudaGetSymbolAddress((void**)&eh, g_eh);
    cudaGetSymbolAddress((void**)&el, g_el);
    cudaGetSymbolAddress((void**)&rh, g_rh);
    cudaGetSymbolAddress((void**)&rl, g_rl);

    auto split = [](const float* x, __nv_bfloat16* hh, __nv_bfloat16* ll, size_t n) {
        k_split<<<(unsigned)((n + 1023) / 1024), 256>>>(x, hh, ll, (int)n);
    };

    k_embed<<<TOK, 256>>>(src, emb);
    k_posemb<<<RL, 256>>>();
    split(emb, eh, el, (size_t)VC * DM);
    split(r, rh, rl, (size_t)RL * DM);

    for (int l = 0; l < NL; l++) {
        const float* Wq = Wqkv + (size_t)l * DM * 3 * DM;
        // qkv = core @ Wqkv[l]  (4096 x 3072 x 1024)
        split(core, ah, al, (size_t)TOK * DM);
        split(Wq, wh, wl, (size_t)DM * 3 * DM);
        k_mgemm<0, false><<<dim3(3 * DM / 128, TOK / 128), 256>>>(
            ah, al, wh, wl, nullptr, big, TOK, 3 * DM, DM);
        // rqkv = r @ Wqkv[l]  (513 x 3072 x 1024)
        k_mgemm<0, false><<<dim3(3 * DM / 128, (RL + 127) / 128), 256>>>(
            rh, rl, wh, wl, nullptr, rqkv, RL, 3 * DM, DM);
        // attention
        k_qr<<<dim3(9, 8, BH), 256>>>();
        k_score<<<dim3(8, 8, BH), 256>>>();
        k_softmax<<<BH * QL, 256>>>();
        k_av<<<dim3(8, BH), 256>>>();
        // attn_out = vec @ Wo[l]
        split(vec, ah, al, (size_t)TOK * DM);
        split(Wo + (size_t)l * DM * DM, wh, wl, (size_t)DM * DM);
        k_mgemm<0, false><<<dim3(DM / 128, TOK / 128), 256>>>(
            ah, al, wh, wl, nullptr, tmp, TOK, DM, DM);
        // src2 = LN(core + attn_out); h = LN(core + src2)
        k_lnres<<<TOK, 256>>>(core, tmp, ln0_g + l * DM, ln0_b + l * DM, vec);
        k_lnres<<<TOK, 256>>>(core, vec, ln1_g + l * DM, ln1_b + l * DM, h);
        // ffn = gelu(h @ W1 + b1) @ W2 + b2
        split(h, ah, al, (size_t)TOK * DM);
        split(W1 + (size_t)l * DM * FFD, wh, wl, (size_t)DM * FFD);
        k_mgemm<1, false><<<dim3(FFD / 128, TOK / 128), 256>>>(
            ah, al, wh, wl, b1 + (size_t)l * FFD, big, TOK, FFD, DM);
        split(big, ah, al, (size_t)TOK * FFD);
        split(W2 + (size_t)l * FFD * DM, wh, wl, (size_t)FFD * DM);
        k_mgemm<0, false><<<dim3(DM / 128, TOK / 128), 256>>>(
            ah, al, wh, wl, b2 + (size_t)l * DM, tmp, TOK, DM, FFD);
        // core = LN(h + ffn)
        k_lnres<<<TOK, 256>>>(h, tmp, ln2_g + l * DM, ln2_b + l * DM, core);
    }

    // logits = core @ emb^T + dec_b  (4096 x 32000 x 1024, NT)
    split(core, ah, al, (size_t)TOK * DM);
    k_mgemm<0, true><<<dim3(VC / 128, TOK / 128), 256>>>(
        ah, al, eh, el, dec_b, out, TOK, VC, DM);
}

// round 8
// speedup vs baseline: 2.3593x; 1.0864x over previous
#include <cuda_runtime.h>
#include <cuda_bf16.h>
#include <math.h>
#include <stdint.h>

// Model dims
#define QL 512
#define BS 8
#define VC 32000
#define DM 1024
#define NH 16
#define DHD 64
#define FFD 4096
#define NL 4
#define RL 513
#define TOK 4096
#define BH 128
#define ATT_SCALE 0.125f

// ---------------------------------------------------------------------------
// Scratch
// ---------------------------------------------------------------------------
__device__ float g_core[TOK * DM];
__device__ float g_big[TOK * FFD];          // QKV output (fp32, read by attention)
__device__ float g_vec[TOK * DM];           // src2 scratch
__device__ float g_tmp[TOK * DM];
__device__ float g_h[TOK * DM];
__device__ float g_r[RL * DM];
__device__ float g_rqkv[RL * 3 * DM];
__device__ float g_qr[(size_t)BH * QL * RL];
__device__ float g_score[(size_t)BH * QL * QL];
// bf16 split buffers
__device__ __nv_bfloat16 g_ah[TOK * FFD];        // FFN1 output split hi
__device__ __nv_bfloat16 g_al[TOK * FFD];        // FFN1 output split lo
__device__ __nv_bfloat16 g_wh[DM * FFD];         // weight split
__device__ __nv_bfloat16 g_wl[DM * FFD];
__device__ __nv_bfloat16 g_eh[(size_t)VC * DM];  // embedding split
__device__ __nv_bfloat16 g_el[(size_t)VC * DM];
__device__ __nv_bfloat16 g_rh[RL * DM];
__device__ __nv_bfloat16 g_rl[RL * DM];
__device__ __nv_bfloat16 g_ch[TOK * DM];         // core split (feeds QKV / logits)
__device__ __nv_bfloat16 g_cl[TOK * DM];
__device__ __nv_bfloat16 g_vh[TOK * DM];         // attn-vec split (feeds Wo)
__device__ __nv_bfloat16 g_vl[TOK * DM];
__device__ __nv_bfloat16 g_hsh[TOK * DM];        // h split (feeds FFN1)
__device__ __nv_bfloat16 g_hsl[TOK * DM];

static __device__ __forceinline__ uint32_t s2u(const void* p) {
    return (uint32_t)__cvta_generic_to_shared(p);
}

#define LDSM4(R, addr)                                                           \
    asm volatile("ldmatrix.sync.aligned.m8n8.x4.shared.b16 {%0,%1,%2,%3}, [%4];" \
                 : "=r"(R[0]), "=r"(R[1]), "=r"(R[2]), "=r"(R[3]) : "r"(addr));
#define LDSM4T(R, addr)                                                                \
    asm volatile("ldmatrix.sync.aligned.m8n8.x4.trans.shared.b16 {%0,%1,%2,%3}, [%4];" \
                 : "=r"(R[0]), "=r"(R[1]), "=r"(R[2]), "=r"(R[3]) : "r"(addr));
#define MMA_BF16(ac, A, b0, b1)                                                  \
    asm volatile("mma.sync.aligned.m16n8k16.row.col.f32.bf16.bf16.f32 "          \
                 "{%0,%1,%2,%3}, {%4,%5,%6,%7}, {%8,%9}, {%0,%1,%2,%3};"         \
                 : "+f"(ac[0]), "+f"(ac[1]), "+f"(ac[2]), "+f"(ac[3])            \
                 : "r"(A[0]), "r"(A[1]), "r"(A[2]), "r"(A[3]), "r"(b0), "r"(b1));

static __device__ __forceinline__ void cp16(__nv_bfloat16* dst,
                                            const __nv_bfloat16* src, bool pred) {
    uint32_t d = s2u(dst);
    int n = pred ? 16 : 0;
    asm volatile("cp.async.cg.shared.global [%0], [%1], 16, %2;" ::"r"(d), "l"(src), "r"(n));
}

static __device__ __forceinline__ void split1(float v, __nv_bfloat16& hi, __nv_bfloat16& lo) {
    hi = __float2bfloat16(v);
    lo = __float2bfloat16(v - __bfloat162float(hi));
}

// ---------------------------------------------------------------------------
// Split fp32 -> (hi, lo) bf16 (weights / embedding / r only now)
// ---------------------------------------------------------------------------
__global__ void k_split(const float* __restrict__ x, __nv_bfloat16* __restrict__ h,
                        __nv_bfloat16* __restrict__ l, int n) {
    int i = (blockIdx.x * 256 + threadIdx.x) * 4;
    if (i >= n) return;
    float4 v = *(const float4*)(x + i);
    __nv_bfloat16 h0, h1, h2, h3, l0, l1, l2, l3;
    split1(v.x, h0, l0); split1(v.y, h1, l1);
    split1(v.z, h2, l2); split1(v.w, h3, l3);
    *(__nv_bfloat162*)(h + i)     = __nv_bfloat162(h0, h1);
    *(__nv_bfloat162*)(h + i + 2) = __nv_bfloat162(h2, h3);
    *(__nv_bfloat162*)(l + i)     = __nv_bfloat162(l0, l1);
    *(__nv_bfloat162*)(l + i + 2) = __nv_bfloat162(l2, l3);
}

// ---------------------------------------------------------------------------
// Split-bf16 tensor-core GEMM, 2-stage cp.async pipeline.
//   C[M,N] = act(A @ op(B) + bias)
//   SPLIT_OUT=false: write fp32 C.  SPLIT_OUT=true: write (Oh,Ol) bf16 split.
//   128x128x32 tile, 8 warps, mma.m16n8k16, 3 MMAs per fragment pair.
// ---------------------------------------------------------------------------
template <int ACT, bool TB, bool SPLIT_OUT>
__global__ __launch_bounds__(256, 2)
void k_mgemm(const __nv_bfloat16* __restrict__ Ah, const __nv_bfloat16* __restrict__ Al,
             const __nv_bfloat16* __restrict__ Bh, const __nv_bfloat16* __restrict__ Bl,
             const float* __restrict__ bias, float* __restrict__ C,
             __nv_bfloat16* __restrict__ Oh, __nv_bfloat16* __restrict__ Ol,
             int M, int N, int K) {
    constexpr int BSTR = TB ? 40 : 136;          // B smem row stride (halves)
    constexpr int ASTG = 128 * 40;               // one A matrix per stage (halves)
    constexpr int BSTG = TB ? 128 * 40 : 32 * 136;
    constexpr int STG = 2 * ASTG + 2 * BSTG;     // full stage (Ah,Al,Bh,Bl)
    extern __shared__ __nv_bfloat16 smem[];

    int tid = threadIdx.x;
    int m0 = blockIdx.y << 7, n0 = blockIdx.x << 7;
    int lane = tid & 31, warp = tid >> 5;
    int wm = warp >> 1, wn = warp & 1;

    float acc[2][8][4];
#pragma unroll
    for (int a = 0; a < 2; a++)
#pragma unroll
        for (int b = 0; b < 8; b++)
#pragma unroll
            for (int c = 0; c < 4; c++) acc[a][b][c] = 0.f;

    // ---- stage loader ----
    auto load_stage = [&](int k0, int s) {
        __nv_bfloat16* sAh = smem + s * STG;
        __nv_bfloat16* sAl = sAh + ASTG;
        __nv_bfloat16* sBh = sAl + ASTG;
        __nv_bfloat16* sBl = sBh + BSTG;
#pragma unroll
        for (int u = 0; u < 2; u++) {
            int p = tid + u * 256;
            int row = p >> 2, kq = (p & 3) << 3;
            bool ok = (m0 + row) < M;
            size_t off = (size_t)(m0 + row) * K + k0 + kq;
            cp16(&sAh[row * 40 + kq], Ah + off, ok);
            cp16(&sAl[row * 40 + kq], Al + off, ok);
        }
#pragma unroll
        for (int u = 0; u < 2; u++) {
            int p = tid + u * 256;
            if (TB) {
                int row = p >> 2, kq = (p & 3) << 3;
                size_t off = (size_t)(n0 + row) * K + k0 + kq;
                cp16(&sBh[row * 40 + kq], Bh + off, true);
                cp16(&sBl[row * 40 + kq], Bl + off, true);
            } else {
                int row = p >> 4, nq = (p & 15) << 3;
                size_t off = (size_t)(k0 + row) * N + n0 + nq;
                cp16(&sBh[row * 136 + nq], Bh + off, true);
                cp16(&sBl[row * 136 + nq], Bl + off, true);
            }
        }
        asm volatile("cp.async.commit_group;");
    };

    int KT = K >> 5;
    load_stage(0, 0);

    for (int kt = 0; kt < KT; kt++) {
        if (kt + 1 < KT) load_stage((kt + 1) << 5, (kt + 1) & 1);
        else asm volatile("cp.async.commit_group;");
        asm volatile("cp.async.wait_group 1;");
        __syncthreads();

        const __nv_bfloat16* sAh = smem + (kt & 1) * STG;
        const __nv_bfloat16* sAl = sAh + ASTG;
        const __nv_bfloat16* sBh = sAl + ASTG;
        const __nv_bfloat16* sBl = sBh + BSTG;

#pragma unroll
        for (int ks = 0; ks < 32; ks += 16) {
            uint32_t ah[2][4], al[2][4];
#pragma unroll
            for (int mt = 0; mt < 2; mt++) {
                int rb = wm * 32 + mt * 16 + (lane & 15);
                int kc = ks + ((lane >> 4) << 3);
                LDSM4(ah[mt], s2u(&sAh[rb * 40 + kc]));
                LDSM4(al[mt], s2u(&sAl[rb * 40 + kc]));
            }
#pragma unroll
            for (int np = 0; np < 4; np++) {
                int nb = wn * 64 + np * 16;
                uint32_t bh[4], bl[4];
                int g = lane >> 3, l8 = lane & 7;
                if (TB) {
                    int nr = nb + ((g >> 1) << 3) + l8;
                    int kc = ks + ((g & 1) << 3);
                    LDSM4(bh, s2u(&sBh[nr * BSTR + kc]));
                    LDSM4(bl, s2u(&sBl[nr * BSTR + kc]));
                } else {
                    int kr = ks + ((g & 1) << 3) + l8;
                    int nc = nb + ((g >> 1) << 3);
                    LDSM4T(bh, s2u(&sBh[kr * BSTR + nc]));
                    LDSM4T(bl, s2u(&sBl[kr * BSTR + nc]));
                }
#pragma unroll
                for (int mt = 0; mt < 2; mt++) {
#pragma unroll
                    for (int j = 0; j < 2; j++) {
                        float* ac = acc[mt][np * 2 + j];
                        MMA_BF16(ac, ah[mt], bh[2 * j], bh[2 * j + 1]);
                        MMA_BF16(ac, ah[mt], bl[2 * j], bl[2 * j + 1]);
                        MMA_BF16(ac, al[mt], bh[2 * j], bh[2 * j + 1]);
                    }
                }
            }
        }
        __syncthreads();
    }

    // ---- epilogue ----
#pragma unroll
    for (int mt = 0; mt < 2; mt++) {
#pragma unroll
        for (int np = 0; np < 4; np++) {
#pragma unroll
            for (int j = 0; j < 2; j++) {
                int nt = np * 2 + j;
                int col = n0 + wn * 64 + np * 16 + j * 8 + (lane & 3) * 2;
                int rb = m0 + wm * 32 + mt * 16 + (lane >> 2);
#pragma unroll
                for (int hh = 0; hh < 2; hh++) {
                    int r = rb + hh * 8;
                    if (r >= M) continue;
                    float v0 = acc[mt][nt][hh * 2];
                    float v1 = acc[mt][nt][hh * 2 + 1];
                    if (bias) { v0 += bias[col]; v1 += bias[col + 1]; }
                    if (ACT == 1) {
                        v0 = 0.5f * v0 * (1.f + erff(v0 * 0.70710678118654752f));
                        v1 = 0.5f * v1 * (1.f + erff(v1 * 0.70710678118654752f));
                    }
                    if (SPLIT_OUT) {
                        __nv_bfloat16 h0, h1, l0, l1;
                        split1(v0, h0, l0);
                        split1(v1, h1, l1);
                        *(__nv_bfloat162*)(Oh + (size_t)r * N + col) = __nv_bfloat162(h0, h1);
                        *(__nv_bfloat162*)(Ol + (size_t)r * N + col) = __nv_bfloat162(l0, l1);
                    } else {
                        *(float2*)(C + (size_t)r * N + col) = make_float2(v0, v1);
                    }
                }
            }
        }
    }
}

// ---------------------------------------------------------------------------
// Embedding lookup * sqrt(D); fused split for QKV input of layer 0
// ---------------------------------------------------------------------------
__global__ void k_embed(const int* __restrict__ src, const float* __restrict__ emb) {
    int t = blockIdx.x;
    int tok = src[t];
    const float4* e = (const float4*)(emb + (size_t)tok * DM);
    size_t base = (size_t)t * DM;
    for (int d = threadIdx.x; d < DM / 4; d += blockDim.x) {
        float4 v = e[d];
        v.x *= 32.f; v.y *= 32.f; v.z *= 32.f; v.w *= 32.f;
        *(float4*)(g_core + base + d * 4) = v;
        __nv_bfloat16 h0, h1, h2, h3, l0, l1, l2, l3;
        split1(v.x, h0, l0); split1(v.y, h1, l1);
        split1(v.z, h2, l2); split1(v.w, h3, l3);
        *(__nv_bfloat162*)(g_ch + base + d * 4)     = __nv_bfloat162(h0, h1);
        *(__nv_bfloat162*)(g_ch + base + d * 4 + 2) = __nv_bfloat162(h2, h3);
        *(__nv_bfloat162*)(g_cl + base + d * 4)     = __nv_bfloat162(l0, l1);
        *(__nv_bfloat162*)(g_cl + base + d * 4 + 2) = __nv_bfloat162(l2, l3);
    }
}

__global__ void k_posemb() {
    int p = blockIdx.x;
    double pos = (double)(QL - p);
    for (int d = threadIdx.x; d < DM; d += blockDim.x) {
        int j = d & 511;
        double inv = exp(-((double)(2 * j) / (double)DM) * log(10000.0));
        double a = pos * inv;
        g_r[p * DM + d] = (d < 512) ? (float)sin(a) : (float)cos(a);
    }
}

// ---------------------------------------------------------------------------
// Attention kernels (fp32)
// ---------------------------------------------------------------------------
__device__ __forceinline__ void mma_nt64(const float (*X)[68], const float (*Y)[68],
                                         int ty, int tx, float acc[4][4]) {
#pragma unroll
    for (int d4 = 0; d4 < 16; d4++) {
        float4 xv[4], yv[4];
#pragma unroll
        for (int ii = 0; ii < 4; ii++) xv[ii] = *(const float4*)&X[ty * 4 + ii][d4 * 4];
#pragma unroll
        for (int jj = 0; jj < 4; jj++) yv[jj] = *(const float4*)&Y[tx * 4 + jj][d4 * 4];
#pragma unroll
        for (int ii = 0; ii < 4; ii++)
#pragma unroll
            for (int jj = 0; jj < 4; jj++)
                acc[ii][jj] += xv[ii].x * yv[jj].x + xv[ii].y * yv[jj].y +
                               xv[ii].z * yv[jj].z + xv[ii].w * yv[jj].w;
    }
}

__global__ __launch_bounds__(256) void k_qr() {
    int bn = blockIdx.z, b = bn >> 4, n = bn & 15;
    int i0 = blockIdx.y << 6, jr0 = blockIdx.x << 6;
    if (jr0 + i0 + 126 < QL) return;
    __shared__ float Qs[64][68], Rs[64][68];
    int tid = threadIdx.x;
    const float* rql = g_rqkv + (size_t)QL * 3 * DM + n * DHD;
#pragma unroll
    for (int u = 0; u < 16; u++) {
        int idx = tid + u * 256;
        int rr = idx >> 6, d = idx & 63;
        Qs[rr][d] = g_big[((size_t)(i0 + rr) * BS + b) * (3 * DM) + n * DHD + d] + rql[d];
        int jr = jr0 + rr;
        Rs[rr][d] = (jr < RL) ? g_rqkv[(size_t)jr * (3 * DM) + DM + n * DHD + d] : 0.f;
    }
    __syncthreads();
    int ty = tid >> 4, tx = tid & 15;
    float acc[4][4] = {};
    mma_nt64(Qs, Rs, ty, tx, acc);
    float* out = g_qr + (size_t)bn * QL * RL;
#pragma unroll
    for (int ii = 0; ii < 4; ii++) {
        int i = i0 + ty * 4 + ii;
#pragma unroll
        for (int jj = 0; jj < 4; jj++) {
            int jr = jr0 + tx * 4 + jj;
            if (jr < RL) out[(size_t)i * RL + jr] = acc[ii][jj];
        }
    }
}

__global__ __launch_bounds__(256) void k_score() {
    int bn = blockIdx.z, b = bn >> 4, n = bn & 15;
    int i0 = blockIdx.y << 6, j0 = blockIdx.x << 6;
    int tid = threadIdx.x, ty = tid >> 4, tx = tid & 15;
    float* srow = g_score + (size_t)bn * QL * QL;
    if (j0 > i0 + 63) {
#pragma unroll
        for (int ii = 0; ii < 4; ii++) {
            int i = i0 + ty * 4 + ii;
            *(float4*)&srow[(size_t)i * QL + j0 + tx * 4] =
                make_float4(-INFINITY, -INFINITY, -INFINITY, -INFINITY);
        }
        return;
    }
    __shared__ float Qs[64][68], Ks[64][68];
    const float* rql = g_rqkv + (size_t)QL * 3 * DM + n * DHD;
#pragma unroll
    for (int u = 0; u < 16; u++) {
        int idx = tid + u * 256;
        int rr = idx >> 6, d = idx & 63;
        Qs[rr][d] = g_big[((size_t)(i0 + rr) * BS + b) * (3 * DM) + n * DHD + d] + rql[d];
        Ks[rr][d] = g_big[((size_t)(j0 + rr) * BS + b) * (3 * DM) + DM + n * DHD + d];
    }
    __syncthreads();
    float acc[4][4] = {};
    mma_nt64(Qs, Ks, ty, tx, acc);
    const float* qrb = g_qr + (size_t)bn * QL * RL;
#pragma unroll
    for (int ii = 0; ii < 4; ii++) {
        int i = i0 + ty * 4 + ii;
        float v[4];
#pragma unroll
        for (int jj = 0; jj < 4; jj++) {
            int j = j0 + tx * 4 + jj;
            if (j > i) v[jj] = -INFINITY;
            else v[jj] = (acc[ii][jj] + qrb[(size_t)i * RL + (QL + j - i)]) * ATT_SCALE;
        }
        *(float4*)&srow[(size_t)i * QL + j0 + tx * 4] = make_float4(v[0], v[1], v[2], v[3]);
    }
}

__global__ __launch_bounds__(256) void k_softmax() {
    float* p = g_score + (size_t)blockIdx.x * QL;
    int tid = threadIdx.x;
    float v0 = p[tid], v1 = p[tid + 256];
    __shared__ float red[256];
    red[tid] = fmaxf(v0, v1);
    __syncthreads();
    for (int st = 128; st > 0; st >>= 1) {
        if (tid < st) red[tid] = fmaxf(red[tid], red[tid + st]);
        __syncthreads();
    }
    float mx = red[0];
    __syncthreads();
    float e0 = expf(v0 - mx), e1 = expf(v1 - mx);
    red[tid] = e0 + e1;
    __syncthreads();
    for (int st = 128; st > 0; st >>= 1) {
        if (tid < st) red[tid] += red[tid + st];
        __syncthreads();
    }
    float inv = 1.f / red[0];
    p[tid] = e0 * inv;
    p[tid + 256] = e1 * inv;
}

// av: writes SPLIT bf16 attention output (feeds Wo GEMM)
__global__ __launch_bounds__(256) void k_av() {
    int bn = blockIdx.y, b = bn >> 4, n = bn & 15;
    int i0 = blockIdx.x << 6;
    __shared__ float Ps[64][68], Vs[64][68];
    int tid = threadIdx.x, ty = tid >> 4, tx = tid & 15;
    float acc[4][4] = {};
    const float* prow = g_score + (size_t)bn * QL * QL;
    int kend = i0 + 64;
    for (int k0 = 0; k0 < kend; k0 += 64) {
#pragma unroll
        for (int u = 0; u < 16; u++) {
            int idx = tid + u * 256;
            int rr = idx >> 6, c = idx & 63;
            Ps[rr][c] = prow[(size_t)(i0 + rr) * QL + k0 + c];
            Vs[rr][c] = g_big[((size_t)(k0 + rr) * BS + b) * (3 * DM) + 2 * DM + n * DHD + c];
        }
        __syncthreads();
#pragma unroll
        for (int k4 = 0; k4 < 16; k4++) {
            float4 pr[4];
#pragma unroll
            for (int ii = 0; ii < 4; ii++) pr[ii] = *(const float4*)&Ps[ty * 4 + ii][k4 * 4];
#pragma unroll
            for (int kk = 0; kk < 4; kk++) {
                float4 vv = *(const float4*)&Vs[k4 * 4 + kk][tx * 4];
#pragma unroll
                for (int ii = 0; ii < 4; ii++) {
                    float pv = ((const float*)&pr[ii])[kk];
                    acc[ii][0] += pv * vv.x;
                    acc[ii][1] += pv * vv.y;
                    acc[ii][2] += pv * vv.z;
                    acc[ii][3] += pv * vv.w;
                }
            }
        }
        __syncthreads();
    }
#pragma unroll
    for (int ii = 0; ii < 4; ii++) {
        int i = i0 + ty * 4 + ii;
        size_t o = ((size_t)i * BS + b) * DM + n * DHD + tx * 4;
        __nv_bfloat16 h0, h1, h2, h3, l0, l1, l2, l3;
        split1(acc[ii][0], h0, l0); split1(acc[ii][1], h1, l1);
        split1(acc[ii][2], h2, l2); split1(acc[ii][3], h3, l3);
        *(__nv_bfloat162*)(g_vh + o)     = __nv_bfloat162(h0, h1);
        *(__nv_bfloat162*)(g_vh + o + 2) = __nv_bfloat162(h2, h3);
        *(__nv_bfloat162*)(g_vl + o)     = __nv_bfloat162(l0, l1);
        *(__nv_bfloat162*)(g_vl + o + 2) = __nv_bfloat162(l2, l3);
    }
}

// ---------------------------------------------------------------------------
// O = LayerNorm(A + B) * gamma + beta; optional fused split outputs
// ---------------------------------------------------------------------------
__global__ __launch_bounds__(256) void k_lnres(const float* __restrict__ A,
                                               const float* __restrict__ Bi,
                                               const float* __restrict__ G,
                                               const float* __restrict__ Be,
                                               float* __restrict__ O,
                                               __nv_bfloat16* __restrict__ Oh,
                                               __nv_bfloat16* __restrict__ Ol) {
    int row = blockIdx.x, tid = threadIdx.x;
    size_t base = (size_t)row * DM + tid * 4;
    float4 va = *(const float4*)(A + base);
    float4 vb = *(const float4*)(Bi + base);
    float x[4] = {va.x + vb.x, va.y + vb.y, va.z + vb.z, va.w + vb.w};
    float s = x[0] + x[1] + x[2] + x[3];
    float s2 = x[0] * x[0] + x[1] * x[1] + x[2] * x[2] + x[3] * x[3];
    __shared__ float rs[256], rs2[256];
    rs[tid] = s;
    rs2[tid] = s2;
    __syncthreads();
    for (int st = 128; st > 0; st >>= 1) {
        if (tid < st) { rs[tid] += rs[tid + st]; rs2[tid] += rs2[tid + st]; }
        __syncthreads();
    }
    float mean = rs[0] * (1.f / (float)DM);
    float var = rs2[0] * (1.f / (float)DM) - mean * mean;
    float inv = rsqrtf(var + 1e-5f);
    float4 g4 = *(const float4*)(G + tid * 4);
    float4 b4 = *(const float4*)(Be + tid * 4);
    float y[4];
    y[0] = (x[0] - mean) * inv * g4.x + b4.x;
    y[1] = (x[1] - mean) * inv * g4.y + b4.y;
    y[2] = (x[2] - mean) * inv * g4.z + b4.z;
    y[3] = (x[3] - mean) * inv * g4.w + b4.w;
    *(float4*)(O + base) = make_float4(y[0], y[1], y[2], y[3]);
    if (Oh) {
        __nv_bfloat16 h0, h1, h2, h3, l0, l1, l2, l3;
        split1(y[0], h0, l0); split1(y[1], h1, l1);
        split1(y[2], h2, l2); split1(y[3], h3, l3);
        *(__nv_bfloat162*)(Oh + base)     = __nv_bfloat162(h0, h1);
        *(__nv_bfloat162*)(Oh + base + 2) = __nv_bfloat162(h2, h3);
        *(__nv_bfloat162*)(Ol + base)     = __nv_bfloat162(l0, l1);
        *(__nv_bfloat162*)(Ol + base + 2) = __nv_bfloat162(l2, l3);
    }
}

// ---------------------------------------------------------------------------
// Launch sequence
// ---------------------------------------------------------------------------
extern "C" void kernel_launch(void* const* d_in, const int* in_sizes, int n_in,
                              void* d_out, int out_size) {
    const int*   src   = (const int*)d_in[0];
    const float* emb   = (const float*)d_in[1];
    const float* dec_b = (const float*)d_in[2];
    const float* Wqkv  = (const float*)d_in[3];
    const float* Wo    = (const float*)d_in[4];
    const float* ln0_g = (const float*)d_in[5];
    const float* ln0_b = (const float*)d_in[6];
    const float* W1    = (const float*)d_in[7];
    const float* b1    = (const float*)d_in[8];
    const float* W2    = (const float*)d_in[9];
    const float* b2    = (const float*)d_in[10];
    const float* ln1_g = (const float*)d_in[11];
    const float* ln1_b = (const float*)d_in[12];
    const float* ln2_g = (const float*)d_in[13];
    const float* ln2_b = (const float*)d_in[14];
    float* out = (float*)d_out;

    float *core, *big, *vec, *tmp, *h, *r, *rqkv;
    cudaGetSymbolAddress((void**)&core, g_core);
    cudaGetSymbolAddress((void**)&big,  g_big);
    cudaGetSymbolAddress((void**)&vec,  g_vec);
    cudaGetSymbolAddress((void**)&tmp,  g_tmp);
    cudaGetSymbolAddress((void**)&h,    g_h);
    cudaGetSymbolAddress((void**)&r,    g_r);
    cudaGetSymbolAddress((void**)&rqkv, g_rqkv);
    __nv_bfloat16 *ah, *al, *wh, *wl, *eh, *el, *rh, *rl, *ch, *cl, *vh, *vl, *hsh, *hsl;
    cudaGetSymbolAddress((void**)&ah,  g_ah);
    cudaGetSymbolAddress((void**)&al,  g_al);
    cudaGetSymbolAddress((void**)&wh,  g_wh);
    cudaGetSymbolAddress((void**)&wl,  g_wl);
    cudaGetSymbolAddress((void**)&eh,  g_eh);
    cudaGetSymbolAddress((void**)&el,  g_el);
    cudaGetSymbolAddress((void**)&rh,  g_rh);
    cudaGetSymbolAddress((void**)&rl,  g_rl);
    cudaGetSymbolAddress((void**)&ch,  g_ch);
    cudaGetSymbolAddress((void**)&cl,  g_cl);
    cudaGetSymbolAddress((void**)&vh,  g_vh);
    cudaGetSymbolAddress((void**)&vl,  g_vl);
    cudaGetSymbolAddress((void**)&hsh, g_hsh);
    cudaGetSymbolAddress((void**)&hsl, g_hsl);

    // dynamic smem opt-in (idempotent)
    const int SMEM_NN = 75776, SMEM_NT = 81920;
    cudaFuncSetAttribute(k_mgemm<0, false, false>,
                         cudaFuncAttributeMaxDynamicSharedMemorySize, SMEM_NN);
    cudaFuncSetAttribute(k_mgemm<1, false, true>,
                         cudaFuncAttributeMaxDynamicSharedMemorySize, SMEM_NN);
    cudaFuncSetAttribute(k_mgemm<0, true, false>,
                         cudaFuncAttributeMaxDynamicSharedMemorySize, SMEM_NT);

    auto split = [](const float* x, __nv_bfloat16* hh, __nv_bfloat16* ll, size_t n) {
        k_split<<<(unsigned)((n + 1023) / 1024), 256>>>(x, hh, ll, (int)n);
    };

    k_embed<<<TOK, 256>>>(src, emb);   // core fp32 + (ch, cl)
    k_posemb<<<RL, 256>>>();
    split(emb, eh, el, (size_t)VC * DM);
    split(r, rh, rl, (size_t)RL * DM);

    for (int l = 0; l < NL; l++) {
        const float* Wq = Wqkv + (size_t)l * DM * 3 * DM;
        split(Wq, wh, wl, (size_t)DM * 3 * DM);
        // qkv = core @ Wqkv[l]
        k_mgemm<0, false, false><<<dim3(3 * DM / 128, TOK / 128), 256, SMEM_NN>>>(
            ch, cl, wh, wl, nullptr, big, nullptr, nullptr, TOK, 3 * DM, DM);
        // rqkv = r @ Wqkv[l]
        k_mgemm<0, false, false><<<dim3(3 * DM / 128, (RL + 127) / 128), 256, SMEM_NN>>>(
            rh, rl, wh, wl, nullptr, rqkv, nullptr, nullptr, RL, 3 * DM, DM);
        // attention
        k_qr<<<dim3(9, 8, BH), 256>>>();
        k_score<<<dim3(8, 8, BH), 256>>>();
        k_softmax<<<BH * QL, 256>>>();
        k_av<<<dim3(8, BH), 256>>>();   // -> (vh, vl)
        // attn_out = vec @ Wo[l]
        split(Wo + (size_t)l * DM * DM, wh, wl, (size_t)DM * DM);
        k_mgemm<0, false, false><<<dim3(DM / 128, TOK / 128), 256, SMEM_NN>>>(
            vh, vl, wh, wl, nullptr, tmp, nullptr, nullptr, TOK, DM, DM);
        // src2 = LN(core + attn_out); h = LN(core + src2) (+ split for FFN1)
        k_lnres<<<TOK, 256>>>(core, tmp, ln0_g + l * DM, ln0_b + l * DM, vec,
                              nullptr, nullptr);
        k_lnres<<<TOK, 256>>>(core, vec, ln1_g + l * DM, ln1_b + l * DM, h, hsh, hsl);
        // ffn hidden = gelu(h @ W1 + b1)  -> split bf16 directly
        split(W1 + (size_t)l * DM * FFD, wh, wl, (size_t)DM * FFD);
        k_mgemm<1, false, true><<<dim3(FFD / 128, TOK / 128), 256, SMEM_NN>>>(
            hsh, hsl, wh, wl, b1 + (size_t)l * FFD, nullptr, ah, al, TOK, FFD, DM);
        // ffn out = hidden @ W2 + b2
        split(W2 + (size_t)l * FFD * DM, wh, wl, (size_t)FFD * DM);
        k_mgemm<0, false, false><<<dim3(DM / 128, TOK / 128), 256, SMEM_NN>>>(
            ah, al, wh, wl, b2 + (size_t)l * DM, tmp, nullptr, nullptr, TOK, DM, FFD);
        // core = LN(h + ffn) (+ split for next QKV / logits)
        k_lnres<<<TOK, 256>>>(h, tmp, ln2_g + l * DM, ln2_b + l * DM, core, ch, cl);
    }

    // logits = core @ emb^T + dec_b
    k_mgemm<0, true, false><<<dim3(VC / 128, TOK / 128), 256, SMEM_NT>>>(
        ch, cl, eh, el, dec_b, out, nullptr, nullptr, TOK, VC, DM);
}